// round 4
// baseline (speedup 1.0000x reference)
#include <cuda_runtime.h>
#include <math.h>
#include <stdint.h>
#include <stddef.h>

// Shapes: x:[32,32768] W1:[32768,2048] b1:[2048] W2:[2048,65536] b2:[65536]
// h = gelu(x@W1+b1); y = h@W2+b2 -> [32][2048][32]; out = batched QR(y).Q

#define NB    32
#define K1    32768
#define HID   2048
#define NOUT  65536
#define NS1   64      // split-K for GEMM1 (chunk 512)
#define NS2   2       // split-K for GEMM2 (chunk 1024)

// ---------------- static device scratch (no allocations) --------------------
__device__ float g_part1[NS1 * NB * HID];     // 16 MB
__device__ float g_h[NB * HID];
__device__ float g_part2[NS2 * NB * NOUT];    // 16 MB
__device__ float g_y[NB * NOUT];              // 8 MB
__device__ float g_Gp[NB * 4 * 1024];         // Gram partials
__device__ float g_P[NB * 1024];              // A-coefficients of Q columns
__device__ float g_Qc[NB * 1024];             // E-coefficients of Q columns

// ---------------- packed f32x2 helpers --------------------------------------
__device__ __forceinline__ unsigned long long f2pack(float lo, float hi) {
    unsigned long long r;
    asm("mov.b64 %0, {%1, %2};" : "=l"(r) : "f"(lo), "f"(hi));
    return r;
}
__device__ __forceinline__ void f2unpack(unsigned long long v, float& lo, float& hi) {
    asm("mov.b64 {%0, %1}, %2;" : "=f"(lo), "=f"(hi) : "l"(v));
}
__device__ __forceinline__ unsigned long long fma2(unsigned long long a,
                                                   unsigned long long b,
                                                   unsigned long long c) {
    unsigned long long d;
    asm("fma.rn.f32x2 %0, %1, %2, %3;" : "=l"(d) : "l"(a), "l"(b), "l"(c));
    return d;
}

// ---------------- GEMM: part[s][m][n] = sum_{k in chunk s} X[m][k] W[k][n] --
// Thread: 16 rows (8 f32x2 accumulators) x 4 cols. CTA(256): 512 cols, 32 rows.
// grid.x = N/512 col blocks, grid.y = split index.
template<int N, int KTOT, int KC, int WHICH>
__global__ void __launch_bounds__(256) gemm_f2(const float* __restrict__ Xin,
                                               const float* __restrict__ W) {
    __shared__ __align__(16) float xs[32][34];
    const float* X = (WHICH == 0) ? Xin : g_h;
    float* part = (WHICH == 0) ? g_part1 : g_part2;

    const int t  = threadIdx.x;
    const int rg = t & 1;              // row group: rows rg*16 .. rg*16+15
    const int nq = t >> 1;             // 0..127
    const int c0 = blockIdx.x * 512 + nq * 4;
    const int s  = blockIdx.y;
    const int k0 = s * KC;

    unsigned long long acc[4][8];
#pragma unroll
    for (int c = 0; c < 4; c++)
#pragma unroll
        for (int i = 0; i < 8; i++) acc[c][i] = 0ull;

    for (int kt = 0; kt < KC; kt += 32) {
        const int kbase = k0 + kt;
        // stage X[0..31][kbase..kbase+31] transposed into xs[kk][m]
#pragma unroll
        for (int i = 0; i < 4; i++) {
            int idx = i * 256 + t;
            int m = idx >> 5, kk = idx & 31;
            xs[kk][m] = X[(size_t)m * KTOT + kbase + kk];
        }
        __syncthreads();
#pragma unroll 8
        for (int kk = 0; kk < 32; kk++) {
            const float4 wv = *reinterpret_cast<const float4*>(
                &W[(size_t)(kbase + kk) * N + c0]);
            unsigned long long w0 = f2pack(wv.x, wv.x);
            unsigned long long w1 = f2pack(wv.y, wv.y);
            unsigned long long w2 = f2pack(wv.z, wv.z);
            unsigned long long w3 = f2pack(wv.w, wv.w);
            const unsigned long long* xp =
                reinterpret_cast<const unsigned long long*>(&xs[kk][rg * 16]);
#pragma unroll
            for (int i = 0; i < 8; i++) {
                unsigned long long xv = xp[i];
                acc[0][i] = fma2(xv, w0, acc[0][i]);
                acc[1][i] = fma2(xv, w1, acc[1][i]);
                acc[2][i] = fma2(xv, w2, acc[2][i]);
                acc[3][i] = fma2(xv, w3, acc[3][i]);
            }
        }
        __syncthreads();
    }
#pragma unroll
    for (int c = 0; c < 4; c++)
#pragma unroll
        for (int i = 0; i < 8; i++) {
            float lo, hi;
            f2unpack(acc[c][i], lo, hi);
            int m = rg * 16 + 2 * i;
            size_t base = ((size_t)(s * 32 + m)) * N + (c0 + c);
            part[base]     = lo;
            part[base + N] = hi;
        }
}

// ---------------- reduce + bias + exact GELU (GEMM1 epilogue) ---------------
__global__ void __launch_bounds__(256) reduce_gelu(const float* __restrict__ b1) {
    int gid = blockIdx.x * 256 + threadIdx.x;     // 0..65535 = m*2048+n
    int n = gid & (HID - 1);
    float sum = b1[n];
#pragma unroll 8
    for (int s = 0; s < NS1; s++) sum += g_part1[(size_t)s * (NB * HID) + gid];
    g_h[gid] = 0.5f * sum * (1.0f + erff(sum * 0.70710678118654752f));
}

// ---------------- reduce + bias (GEMM2 epilogue) ----------------------------
__global__ void __launch_bounds__(256) reduce_bias(const float* __restrict__ b2) {
    int gid = blockIdx.x * 256 + threadIdx.x;     // 0..2097151 = m*65536+n
    int n = gid & (NOUT - 1);
    g_y[gid] = g_part2[gid] + g_part2[(size_t)(NB * NOUT) + gid] + b2[n];
}

// ---------------- Gram partials: Gp[b*4+s] = A_chunk^T A_chunk --------------
__global__ void __launch_bounds__(256) gram_kernel() {
    __shared__ __align__(16) float sh[64][36];
    const int b = blockIdx.x >> 2, s = blockIdx.x & 3;
    const int t = threadIdx.x;
    const int i  = t >> 3;          // 0..31
    const int j0 = (t * 4) & 31;    // 0,4,...,28
    float a0 = 0.f, a1 = 0.f, a2 = 0.f, a3 = 0.f;
    for (int chunk = 0; chunk < 8; chunk++) {
        int rowbase = s * 512 + chunk * 64;
#pragma unroll
        for (int l = 0; l < 8; l++) {
            int idx = l * 256 + t;
            int rl = idx >> 5, c = idx & 31;
            sh[rl][c] = g_y[(size_t)b * NOUT + (rowbase + rl) * 32 + c];
        }
        __syncthreads();
#pragma unroll 16
        for (int kk = 0; kk < 64; kk++) {
            float ai = sh[kk][i];
            float4 aj = *reinterpret_cast<const float4*>(&sh[kk][j0]);
            a0 += ai * aj.x; a1 += ai * aj.y; a2 += ai * aj.z; a3 += ai * aj.w;
        }
        __syncthreads();
    }
    size_t o = (size_t)(b * 4 + s) * 1024 + i * 32 + j0;
    g_Gp[o] = a0; g_Gp[o + 1] = a1; g_Gp[o + 2] = a2; g_Gp[o + 3] = a3;
}

// ---------------- Householder QR recurrence in 64-dim coefficient space -----
// One warp per batch. Thread t owns column t's coefficients (p: A-part, q: E-part).
// Exactly simulates LAPACK slarfg/geqrf + orgqr, so signs match jnp.linalg.qr.
__global__ void __launch_bounds__(32) qr_recur() {
    const int b = blockIdx.x;
    const int t = threadIdx.x;
    __shared__ float sG[32][33], sT[32][33];
    __shared__ float Vp[32][32], Vq[32][32], GH[32][32], TH[32][32];
    __shared__ float stau[32];
    __shared__ float pj[32], qj[32], spv[32], sqv[32];

    // load G (reduce 4 split partials) and T = A[0:32,:]
    for (int j = 0; j < 32; j++) {
        float g = 0.f;
#pragma unroll
        for (int s = 0; s < 4; s++) g += g_Gp[(size_t)(b * 4 + s) * 1024 + t * 32 + j];
        sG[t][j] = g;
        sT[t][j] = g_y[(size_t)b * NOUT + t * 32 + j];
    }
    __syncwarp();

    float p[32], q[32];
#pragma unroll
    for (int r = 0; r < 32; r++) { p[r] = (r == t) ? 1.f : 0.f; q[r] = 0.f; }

    // forward: geqrf
    for (int j = 0; j < 32; j++) {
        if (t == j) {
#pragma unroll
            for (int r = 0; r < 32; r++) { pj[r] = p[r]; qj[r] = q[r]; }
        }
        __syncwarp();
        float u = 0.f, gp = 0.f;
#pragma unroll
        for (int r = 0; r < 32; r++) { u += sT[t][r] * pj[r]; gp += sG[t][r] * pj[r]; }
        float h = u + qj[t];                               // head_t of column j
        float term  = pj[t] * gp + qj[t] * (2.f * u + qj[t]);
        float hterm = (t < j) ? h * h : 0.f;
#pragma unroll
        for (int off = 16; off; off >>= 1) {
            term  += __shfl_xor_sync(0xffffffffu, term, off);
            hterm += __shfl_xor_sync(0xffffffffu, hterm, off);
        }
        float sigma = term - hterm;                        // ||tail||^2 incl alpha
        float alpha = __shfl_sync(0xffffffffu, h, j);
        float nrm = sqrtf(fmaxf(sigma, 0.f));
        float beta = (alpha >= 0.f) ? -nrm : nrm;          // -sign(alpha)*norm
        float inv  = 1.f / (alpha - beta);
        float tauj = (beta - alpha) / beta;
        float pv = pj[t] * inv;
        float qv;
        if (t < j)       qv = (qj[t] - h) * inv;           // zero the head rows
        else if (t == j) qv = (qj[t] - beta) * inv;        // v[j] = 1 after scaling
        else             qv = qj[t] * inv;
        spv[t] = pv; sqv[t] = qv;
        Vp[j][t] = pv; Vq[j][t] = qv;
        if (t == 0) stau[j] = tauj;
        __syncwarp();
        float tpv = 0.f, gpv = 0.f, ttqv = 0.f;
#pragma unroll
        for (int r = 0; r < 32; r++) {
            tpv  += sT[t][r] * spv[r];
            gpv  += sG[t][r] * spv[r];
            ttqv += sT[r][t] * sqv[r];
        }
        GH[j][t] = gpv + ttqv;     // (G pv + T^T qv)[t]
        TH[j][t] = tpv + sqv[t];   // (T pv + qv)[t]
        __syncwarp();
        if (t > j) {
            float w = 0.f;
#pragma unroll
            for (int r = 0; r < 32; r++) w += GH[j][r] * p[r] + TH[j][r] * q[r];
            float sc = tauj * w;
#pragma unroll
            for (int r = 0; r < 32; r++) { p[r] -= sc * Vp[j][r]; q[r] -= sc * Vq[j][r]; }
        }
        __syncwarp();
    }

    // backward: orgqr on [I_n; 0]
#pragma unroll
    for (int r = 0; r < 32; r++) { p[r] = 0.f; q[r] = (r == t) ? 1.f : 0.f; }
    for (int j = 31; j >= 0; j--) {
        float w = 0.f;
#pragma unroll
        for (int r = 0; r < 32; r++) w += GH[j][r] * p[r] + TH[j][r] * q[r];
        float sc = stau[j] * w;
#pragma unroll
        for (int r = 0; r < 32; r++) { p[r] -= sc * Vp[j][r]; q[r] -= sc * Vq[j][r]; }
    }
#pragma unroll
    for (int r = 0; r < 32; r++) {
        g_P [(size_t)b * 1024 + r * 32 + t] = p[r];
        g_Qc[(size_t)b * 1024 + r * 32 + t] = q[r];
    }
}

// ---------------- Q = A P + E Qc --------------------------------------------
__global__ void __launch_bounds__(256) formq(float* __restrict__ out) {
    __shared__ float sA[64][33];
    __shared__ float sP[32][33], sQ[32][33];
    const int b = blockIdx.y, rb = blockIdx.x;
    const int t = threadIdx.x;
    const int w = t >> 5, lane = t & 31;
#pragma unroll
    for (int l = 0; l < 8; l++) {
        int idx = l * 256 + t;
        int rl = idx >> 5, c = idx & 31;
        sA[rl][c] = g_y[(size_t)b * NOUT + (rb * 64 + rl) * 32 + c];
    }
#pragma unroll
    for (int l = 0; l < 4; l++) {
        int idx = l * 256 + t;
        int k = idx >> 5, c = idx & 31;
        sP[k][c] = g_P [(size_t)b * 1024 + idx];
        sQ[k][c] = g_Qc[(size_t)b * 1024 + idx];
    }
    __syncthreads();
#pragma unroll
    for (int rr = 0; rr < 8; rr++) {
        int rl = w * 8 + rr;
        float acc = 0.f;
#pragma unroll
        for (int k = 0; k < 32; k++) acc += sA[rl][k] * sP[k][lane];
        int rg = rb * 64 + rl;
        if (rg < 32) acc += sQ[rg][lane];
        out[(size_t)b * NOUT + rg * 32 + lane] = acc;
    }
}

// ---------------- launch ----------------------------------------------------
extern "C" void kernel_launch(void* const* d_in, const int* in_sizes, int n_in,
                              void* d_out, int out_size) {
    const float* x  = (const float*)d_in[0];
    const float* W1 = (const float*)d_in[1];
    const float* b1 = (const float*)d_in[2];
    const float* W2 = (const float*)d_in[3];
    const float* b2 = (const float*)d_in[4];
    float* out = (float*)d_out;
    (void)in_sizes; (void)n_in; (void)out_size;

    gemm_f2<HID, K1, K1 / NS1, 0><<<dim3(HID / 512, NS1), 256>>>(x, W1);
    reduce_gelu<<<(NB * HID) / 256, 256>>>(b1);
    gemm_f2<NOUT, HID, HID / NS2, 1><<<dim3(NOUT / 512, NS2), 256>>>(x, W2);
    reduce_bias<<<(NB * NOUT) / 256, 256>>>(b2);
    gram_kernel<<<NB * 4, 256>>>();
    qr_recur<<<NB, 32>>>();
    formq<<<dim3(32, NB), 256>>>(out);
}

// round 6
// speedup vs baseline: 1.7852x; 1.7852x over previous
#include <cuda_runtime.h>
#include <math.h>
#include <stdint.h>
#include <stddef.h>

// Shapes: x:[32,32768] W1:[32768,2048] b1:[2048] W2:[2048,65536] b2:[65536]
// h = gelu(x@W1+b1); y = h@W2+b2 -> [32][2048][32]; out = batched QR(y).Q

#define NB    32
#define K1    32768
#define HID   2048
#define NOUT  65536
#define KC    512          // K chunk per CTA (both GEMMs)
#define NCOL  256          // columns per CTA
#define NS1   (K1 / KC)    // 64 splits for GEMM1
#define NS2   (HID / KC)   // 4 splits for GEMM2
#define DEPTH 3            // cp.async ring depth

// ---------------- static device scratch (no allocations) --------------------
__device__ float g_part1[NS1 * NB * HID];     // 16 MB
__device__ float g_h[NB * HID];
__device__ float g_part2[NS2 * NB * NOUT];    // 32 MB
__device__ float g_y[NB * NOUT];              // 8 MB
__device__ float g_Gp[NB * 4 * 1024];
__device__ float g_P[NB * 1024];
__device__ float g_Qc[NB * 1024];

// ---------------- smem layout (bytes) ---------------------------------------
#define XP_STRIDE 260                                  // u32/row: 256 + 4 pad
#define SM_XPHI   0
#define SM_XPLO   (32 * XP_STRIDE * 4)                 // 33280
#define SM_WSTG   (2 * 32 * XP_STRIDE * 4)             // 66560
#define WSTG_B    (32 * 256 * 4)                       // 32768 per stage
#define WP_STRIDE 264                                  // u32/row: 256 + 8 pad
#define SM_WPHI   (SM_WSTG + DEPTH * WSTG_B)           // 164864
#define SM_WPLO   (SM_WPHI + 16 * WP_STRIDE * 4)       // 181760
#define SM_TOTAL  (SM_WPLO + 16 * WP_STRIDE * 4)       // 198656

// ---------------- helpers ----------------------------------------------------
__device__ __forceinline__ uint32_t smem_u32(const void* p) {
    uint32_t a;
    asm("{ .reg .u64 t; cvta.to.shared.u64 t, %1; cvt.u32.u64 %0, t; }"
        : "=r"(a) : "l"(p));
    return a;
}
// pack two fp32 -> bf16x2, LOW half = first (lower-k) element
__device__ __forceinline__ uint32_t pack_bf16(float lo_elt, float hi_elt) {
    uint32_t r;
    asm("cvt.rn.bf16x2.f32 %0, %1, %2;" : "=r"(r) : "f"(hi_elt), "f"(lo_elt));
    return r;
}
// split (x0,x1) into hi bf16x2 and lo bf16x2 (x = hi + lo + O(2^-17))
__device__ __forceinline__ void split2(float x0, float x1,
                                       uint32_t& hi, uint32_t& lo) {
    uint32_t h = pack_bf16(x0, x1);
    float h0 = __uint_as_float(h << 16);
    float h1 = __uint_as_float(h & 0xFFFF0000u);
    lo = pack_bf16(x0 - h0, x1 - h1);
    hi = h;
}
__device__ __forceinline__ void mma16816(float* c, const uint32_t* a,
                                         const uint32_t* b) {
    asm volatile(
        "mma.sync.aligned.m16n8k16.row.col.f32.bf16.bf16.f32 "
        "{%0,%1,%2,%3}, {%4,%5,%6,%7}, {%8,%9}, {%0,%1,%2,%3};"
        : "+f"(c[0]), "+f"(c[1]), "+f"(c[2]), "+f"(c[3])
        : "r"(a[0]), "r"(a[1]), "r"(a[2]), "r"(a[3]), "r"(b[0]), "r"(b[1]));
}
__device__ __forceinline__ void cp16(uint32_t saddr, const void* g) {
    asm volatile("cp.async.cg.shared.global [%0], [%1], 16;\n"
                 :: "r"(saddr), "l"(g));
}

// ---------------- GEMM: part[s][m][n] += X[m][k] W[k][n], tensor cores ------
template<int N, int KTOT, int WHICH>
__global__ void __launch_bounds__(256, 1) mma_gemm(const float* __restrict__ Xg,
                                                   const float* __restrict__ W) {
    extern __shared__ char smem[];
    const uint32_t sbase = smem_u32(smem);
    const float* X = (WHICH == 0) ? Xg : g_h;
    float* part = (WHICH == 0) ? g_part1 : g_part2;

    const int t = threadIdx.x;
    const int warp = t >> 5, lane = t & 31;
    const int g = lane >> 2, q = lane & 3;
    const int c0 = blockIdx.x * NCOL;
    const int s = blockIdx.y;
    const int k0 = s * KC;

    uint32_t* xp_hi = (uint32_t*)(smem + SM_XPHI);
    uint32_t* xp_lo = (uint32_t*)(smem + SM_XPLO);
    uint32_t* wp_hi = (uint32_t*)(smem + SM_WPHI);
    uint32_t* wp_lo = (uint32_t*)(smem + SM_WPLO);

    // ---- stage X chunk [32][KC] -> packed bf16x2 hi/lo ----
#pragma unroll
    for (int i = 0; i < 16; i++) {
        int id = i * 256 + t;                 // 0..4095
        int m = id >> 7, c4 = id & 127;
        float4 v = *(const float4*)&X[(size_t)m * KTOT + k0 + c4 * 4];
        uint32_t h0, l0, h1, l1;
        split2(v.x, v.y, h0, l0);
        split2(v.z, v.w, h1, l1);
        int o = m * XP_STRIDE + c4 * 2;
        *(uint2*)&xp_hi[o] = make_uint2(h0, h1);
        *(uint2*)&xp_lo[o] = make_uint2(l0, l1);
    }

    // ---- prologue: prefetch DEPTH W stages ([32][256] fp32 each) ----
    const int NSTEP = KC / 32;                // 16
#pragma unroll
    for (int d = 0; d < DEPTH; d++) {
#pragma unroll
        for (int i = 0; i < 8; i++) {
            int f = (i * 256 + t) * 4;        // float index in stage
            int r = f >> 8, c = f & 255;
            cp16(sbase + SM_WSTG + d * WSTG_B + f * 4,
                 &W[(size_t)(k0 + d * 32 + r) * N + (c0 + c)]);
        }
        asm volatile("cp.async.commit_group;\n");
    }

    float acc[2][4][4];
#pragma unroll
    for (int mt = 0; mt < 2; mt++)
#pragma unroll
        for (int nt = 0; nt < 4; nt++)
#pragma unroll
            for (int i = 0; i < 4; i++) acc[mt][nt][i] = 0.f;

    for (int st = 0; st < NSTEP; st++) {
        const int d = st % DEPTH;
        asm volatile("cp.async.wait_group %0;\n" :: "n"(DEPTH - 1));
        __syncthreads();

        // ---- convert W stage -> packed bf16x2 hi/lo in fragment order ----
        const float* ws = (const float*)(smem + SM_WSTG + d * WSTG_B);
#pragma unroll
        for (int i = 0; i < 4; i++) {
            int id = i * 256 + t;             // 0..1023
            int pr = id >> 6, c4 = id & 63;   // pr = k/2 (0..15)
            float4 ev = *(const float4*)&ws[(2 * pr) * 256 + c4 * 4];
            float4 ov = *(const float4*)&ws[(2 * pr + 1) * 256 + c4 * 4];
            uint32_t h[4], l[4];
            split2(ev.x, ov.x, h[0], l[0]);
            split2(ev.y, ov.y, h[1], l[1]);
            split2(ev.z, ov.z, h[2], l[2]);
            split2(ev.w, ov.w, h[3], l[3]);
            int base = pr * WP_STRIDE + c4 * 4;
            *(uint4*)&wp_hi[base] = make_uint4(h[0], h[1], h[2], h[3]);
            *(uint4*)&wp_lo[base] = make_uint4(l[0], l[1], l[2], l[3]);
        }
        __syncthreads();

        // ---- prefetch stage st+DEPTH into ring slot d ----
        // NOTE: commit EVERY step (empty group in the tail) so the FIFO
        // invariant committed==DEPTH+st holds and wait_group(DEPTH-1)
        // really guarantees stage st has landed (round-5 tail-drain bug).
        if (st + DEPTH < NSTEP) {
#pragma unroll
            for (int i = 0; i < 8; i++) {
                int f = (i * 256 + t) * 4;
                int r = f >> 8, c = f & 255;
                cp16(sbase + SM_WSTG + d * WSTG_B + f * 4,
                     &W[(size_t)(k0 + (st + DEPTH) * 32 + r) * N + (c0 + c)]);
            }
        }
        asm volatile("cp.async.commit_group;\n");

        // ---- two k16 MMA sub-steps ----
#pragma unroll
        for (int j = 0; j < 2; j++) {
            const int r0 = st * 16 + j * 8;   // Xp column base (k/2)
            uint32_t ah[2][4], al[2][4];
#pragma unroll
            for (int mt = 0; mt < 2; mt++) {
                int mb = mt * 16;
                ah[mt][0] = xp_hi[(mb + g) * XP_STRIDE + r0 + q];
                ah[mt][1] = xp_hi[(mb + g + 8) * XP_STRIDE + r0 + q];
                ah[mt][2] = xp_hi[(mb + g) * XP_STRIDE + r0 + q + 4];
                ah[mt][3] = xp_hi[(mb + g + 8) * XP_STRIDE + r0 + q + 4];
                al[mt][0] = xp_lo[(mb + g) * XP_STRIDE + r0 + q];
                al[mt][1] = xp_lo[(mb + g + 8) * XP_STRIDE + r0 + q];
                al[mt][2] = xp_lo[(mb + g) * XP_STRIDE + r0 + q + 4];
                al[mt][3] = xp_lo[(mb + g + 8) * XP_STRIDE + r0 + q + 4];
            }
#pragma unroll
            for (int nt = 0; nt < 4; nt++) {
                int nc = warp * 32 + nt * 8 + g;
                uint32_t bh[2], bl[2];
                bh[0] = wp_hi[(j * 8 + q) * WP_STRIDE + nc];
                bh[1] = wp_hi[(j * 8 + q + 4) * WP_STRIDE + nc];
                bl[0] = wp_lo[(j * 8 + q) * WP_STRIDE + nc];
                bl[1] = wp_lo[(j * 8 + q + 4) * WP_STRIDE + nc];
#pragma unroll
                for (int mt = 0; mt < 2; mt++) {
                    mma16816(acc[mt][nt], ah[mt], bh);   // hi*hi
                    mma16816(acc[mt][nt], ah[mt], bl);   // hi*lo
                    mma16816(acc[mt][nt], al[mt], bh);   // lo*hi
                }
            }
        }
    }

    // ---- store partials ----
#pragma unroll
    for (int mt = 0; mt < 2; mt++)
#pragma unroll
        for (int nt = 0; nt < 4; nt++) {
            int m = mt * 16 + g;
            int n = c0 + warp * 32 + nt * 8 + 2 * q;
            size_t b0 = ((size_t)(s * 32 + m)) * N + n;
            part[b0]     = acc[mt][nt][0];
            part[b0 + 1] = acc[mt][nt][1];
            size_t b1 = b0 + (size_t)8 * N;
            part[b1]     = acc[mt][nt][2];
            part[b1 + 1] = acc[mt][nt][3];
        }
}

// ---------------- reduce + bias + exact GELU (GEMM1 epilogue) ---------------
__global__ void __launch_bounds__(256) reduce_gelu(const float* __restrict__ b1) {
    int gid = blockIdx.x * 256 + threadIdx.x;
    int n = gid & (HID - 1);
    float sum = b1[n];
#pragma unroll 8
    for (int s = 0; s < NS1; s++) sum += g_part1[(size_t)s * (NB * HID) + gid];
    g_h[gid] = 0.5f * sum * (1.0f + erff(sum * 0.70710678118654752f));
}

// ---------------- reduce + bias (GEMM2 epilogue) ----------------------------
__global__ void __launch_bounds__(256) reduce_bias(const float* __restrict__ b2) {
    int gid = blockIdx.x * 256 + threadIdx.x;
    int n = gid & (NOUT - 1);
    float sum = b2[n];
#pragma unroll
    for (int s = 0; s < NS2; s++) sum += g_part2[(size_t)s * (NB * NOUT) + gid];
    g_y[gid] = sum;
}

// ---------------- Gram partials: Gp[b*4+s] = A_chunk^T A_chunk --------------
__global__ void __launch_bounds__(256) gram_kernel() {
    __shared__ __align__(16) float sh[64][36];
    const int b = blockIdx.x >> 2, s = blockIdx.x & 3;
    const int t = threadIdx.x;
    const int i  = t >> 3;
    const int j0 = (t * 4) & 31;
    float a0 = 0.f, a1 = 0.f, a2 = 0.f, a3 = 0.f;
    for (int chunk = 0; chunk < 8; chunk++) {
        int rowbase = s * 512 + chunk * 64;
#pragma unroll
        for (int l = 0; l < 8; l++) {
            int idx = l * 256 + t;
            int rl = idx >> 5, c = idx & 31;
            sh[rl][c] = g_y[(size_t)b * NOUT + (rowbase + rl) * 32 + c];
        }
        __syncthreads();
#pragma unroll 16
        for (int kk = 0; kk < 64; kk++) {
            float ai = sh[kk][i];
            float4 aj = *reinterpret_cast<const float4*>(&sh[kk][j0]);
            a0 += ai * aj.x; a1 += ai * aj.y; a2 += ai * aj.z; a3 += ai * aj.w;
        }
        __syncthreads();
    }
    size_t o = (size_t)(b * 4 + s) * 1024 + i * 32 + j0;
    g_Gp[o] = a0; g_Gp[o + 1] = a1; g_Gp[o + 2] = a2; g_Gp[o + 3] = a3;
}

// ---------------- Householder QR recurrence in 64-dim coefficient space -----
__global__ void __launch_bounds__(32) qr_recur() {
    const int b = blockIdx.x;
    const int t = threadIdx.x;
    __shared__ float sG[32][33], sT[32][33];
    __shared__ float Vp[32][32], Vq[32][32], GH[32][32], TH[32][32];
    __shared__ float stau[32];
    __shared__ float pj[32], qj[32], spv[32], sqv[32];

    for (int j = 0; j < 32; j++) {
        float g = 0.f;
#pragma unroll
        for (int s = 0; s < 4; s++) g += g_Gp[(size_t)(b * 4 + s) * 1024 + t * 32 + j];
        sG[t][j] = g;
        sT[t][j] = g_y[(size_t)b * NOUT + t * 32 + j];
    }
    __syncwarp();

    float p[32], q[32];
#pragma unroll
    for (int r = 0; r < 32; r++) { p[r] = (r == t) ? 1.f : 0.f; q[r] = 0.f; }

    for (int j = 0; j < 32; j++) {
        if (t == j) {
#pragma unroll
            for (int r = 0; r < 32; r++) { pj[r] = p[r]; qj[r] = q[r]; }
        }
        __syncwarp();
        float u = 0.f, gp = 0.f;
#pragma unroll
        for (int r = 0; r < 32; r++) { u += sT[t][r] * pj[r]; gp += sG[t][r] * pj[r]; }
        float h = u + qj[t];
        float term  = pj[t] * gp + qj[t] * (2.f * u + qj[t]);
        float hterm = (t < j) ? h * h : 0.f;
#pragma unroll
        for (int off = 16; off; off >>= 1) {
            term  += __shfl_xor_sync(0xffffffffu, term, off);
            hterm += __shfl_xor_sync(0xffffffffu, hterm, off);
        }
        float sigma = term - hterm;
        float alpha = __shfl_sync(0xffffffffu, h, j);
        float nrm = sqrtf(fmaxf(sigma, 0.f));
        float beta = (alpha >= 0.f) ? -nrm : nrm;
        float inv  = 1.f / (alpha - beta);
        float tauj = (beta - alpha) / beta;
        float pv = pj[t] * inv;
        float qv;
        if (t < j)       qv = (qj[t] - h) * inv;
        else if (t == j) qv = (qj[t] - beta) * inv;
        else             qv = qj[t] * inv;
        spv[t] = pv; sqv[t] = qv;
        Vp[j][t] = pv; Vq[j][t] = qv;
        if (t == 0) stau[j] = tauj;
        __syncwarp();
        float tpv = 0.f, gpv = 0.f, ttqv = 0.f;
#pragma unroll
        for (int r = 0; r < 32; r++) {
            tpv  += sT[t][r] * spv[r];
            gpv  += sG[t][r] * spv[r];
            ttqv += sT[r][t] * sqv[r];
        }
        GH[j][t] = gpv + ttqv;
        TH[j][t] = tpv + sqv[t];
        __syncwarp();
        if (t > j) {
            float w = 0.f;
#pragma unroll
            for (int r = 0; r < 32; r++) w += GH[j][r] * p[r] + TH[j][r] * q[r];
            float sc = tauj * w;
#pragma unroll
            for (int r = 0; r < 32; r++) { p[r] -= sc * Vp[j][r]; q[r] -= sc * Vq[j][r]; }
        }
        __syncwarp();
    }

#pragma unroll
    for (int r = 0; r < 32; r++) { p[r] = 0.f; q[r] = (r == t) ? 1.f : 0.f; }
    for (int j = 31; j >= 0; j--) {
        float w = 0.f;
#pragma unroll
        for (int r = 0; r < 32; r++) w += GH[j][r] * p[r] + TH[j][r] * q[r];
        float sc = stau[j] * w;
#pragma unroll
        for (int r = 0; r < 32; r++) { p[r] -= sc * Vp[j][r]; q[r] -= sc * Vq[j][r]; }
    }
#pragma unroll
    for (int r = 0; r < 32; r++) {
        g_P [(size_t)b * 1024 + r * 32 + t] = p[r];
        g_Qc[(size_t)b * 1024 + r * 32 + t] = q[r];
    }
}

// ---------------- Q = A P + E Qc --------------------------------------------
__global__ void __launch_bounds__(256) formq(float* __restrict__ out) {
    __shared__ float sA[64][33];
    __shared__ float sP[32][33], sQ[32][33];
    const int b = blockIdx.y, rb = blockIdx.x;
    const int t = threadIdx.x;
    const int w = t >> 5, lane = t & 31;
#pragma unroll
    for (int l = 0; l < 8; l++) {
        int idx = l * 256 + t;
        int rl = idx >> 5, c = idx & 31;
        sA[rl][c] = g_y[(size_t)b * NOUT + (rb * 64 + rl) * 32 + c];
    }
#pragma unroll
    for (int l = 0; l < 4; l++) {
        int idx = l * 256 + t;
        int k = idx >> 5, c = idx & 31;
        sP[k][c] = g_P [(size_t)b * 1024 + idx];
        sQ[k][c] = g_Qc[(size_t)b * 1024 + idx];
    }
    __syncthreads();
#pragma unroll
    for (int rr = 0; rr < 8; rr++) {
        int rl = w * 8 + rr;
        float acc = 0.f;
#pragma unroll
        for (int k = 0; k < 32; k++) acc += sA[rl][k] * sP[k][lane];
        int rg = rb * 64 + rl;
        if (rg < 32) acc += sQ[rg][lane];
        out[(size_t)b * NOUT + rg * 32 + lane] = acc;
    }
}

// ---------------- launch ----------------------------------------------------
extern "C" void kernel_launch(void* const* d_in, const int* in_sizes, int n_in,
                              void* d_out, int out_size) {
    const float* x  = (const float*)d_in[0];
    const float* W1 = (const float*)d_in[1];
    const float* b1 = (const float*)d_in[2];
    const float* W2 = (const float*)d_in[3];
    const float* b2 = (const float*)d_in[4];
    float* out = (float*)d_out;
    (void)in_sizes; (void)n_in; (void)out_size;

    cudaFuncSetAttribute(mma_gemm<HID, K1, 0>,
                         cudaFuncAttributeMaxDynamicSharedMemorySize, SM_TOTAL);
    cudaFuncSetAttribute(mma_gemm<NOUT, HID, 1>,
                         cudaFuncAttributeMaxDynamicSharedMemorySize, SM_TOTAL);

    mma_gemm<HID, K1, 0><<<dim3(HID / NCOL, NS1), 256, SM_TOTAL>>>(x, W1);
    reduce_gelu<<<(NB * HID) / 256, 256>>>(b1);
    mma_gemm<NOUT, HID, 1><<<dim3(NOUT / NCOL, NS2), 256, SM_TOTAL>>>(x, W2);
    reduce_bias<<<(NB * NOUT) / 256, 256>>>(b2);
    gram_kernel<<<NB * 4, 256>>>();
    qr_recur<<<NB, 32>>>();
    formq<<<dim3(32, NB), 256>>>(out);
}